// round 5
// baseline (speedup 1.0000x reference)
#include <cuda_runtime.h>
#include <cuda_bf16.h>
#include <cstdint>
#include <math.h>

// Problem constants
#define DMODEL 1024
#define NBATCH 8
#define SEQ    2048
#define NTOK   (NBATCH * SEQ)   // 16384

// split-bf16 global scratch
__device__ __nv_bfloat16 g_Xhi[NTOK * DMODEL];
__device__ __nv_bfloat16 g_Xlo[NTOK * DMODEL];
__device__ __nv_bfloat16 g_Wthi[3 * DMODEL * DMODEL];  // W^T, [z][n][k]
__device__ __nv_bfloat16 g_Wtlo[3 * DMODEL * DMODEL];
__device__ __nv_bfloat16 g_Qhi[NTOK * DMODEL];
__device__ __nv_bfloat16 g_Qlo[NTOK * DMODEL];
__device__ __nv_bfloat16 g_Khi[NTOK * DMODEL];
__device__ __nv_bfloat16 g_Klo[NTOK * DMODEL];
__device__ __nv_bfloat16 g_Vhi[NTOK * DMODEL];
__device__ __nv_bfloat16 g_Vlo[NTOK * DMODEL];

// ===========================================================================
// helpers
// ===========================================================================
__device__ __forceinline__ uint32_t smem_to_u32(const void* p) {
    uint32_t a;
    asm("{ .reg .u64 t; cvta.to.shared.u64 t, %1; cvt.u32.u64 %0, t; }" : "=r"(a) : "l"(p));
    return a;
}
__device__ __forceinline__ void cpa16(uint32_t d, const void* s) {
    asm volatile("cp.async.cg.shared.global [%0], [%1], 16;" :: "r"(d), "l"(s));
}
#define CP_COMMIT() asm volatile("cp.async.commit_group;")
#define CP_WAIT(N)  asm volatile("cp.async.wait_group %0;" :: "n"(N))

__device__ __forceinline__ void ldsm_x4(uint32_t r[4], uint32_t a) {
    asm volatile("ldmatrix.sync.aligned.m8n8.x4.shared.b16 {%0,%1,%2,%3}, [%4];"
        : "=r"(r[0]), "=r"(r[1]), "=r"(r[2]), "=r"(r[3]) : "r"(a));
}
__device__ __forceinline__ void ldsm_x2(uint32_t r[2], uint32_t a) {
    asm volatile("ldmatrix.sync.aligned.m8n8.x2.shared.b16 {%0,%1}, [%2];"
        : "=r"(r[0]), "=r"(r[1]) : "r"(a));
}
__device__ __forceinline__ void ldsm_x2t(uint32_t r[2], uint32_t a) {
    asm volatile("ldmatrix.sync.aligned.m8n8.x2.trans.shared.b16 {%0,%1}, [%2];"
        : "=r"(r[0]), "=r"(r[1]) : "r"(a));
}
__device__ __forceinline__ void mma_bf16(float c[4], const uint32_t a[4], const uint32_t b[2]) {
    asm volatile("mma.sync.aligned.m16n8k16.row.col.f32.bf16.bf16.f32 "
        "{%0,%1,%2,%3}, {%4,%5,%6,%7}, {%8,%9}, {%0,%1,%2,%3};"
        : "+f"(c[0]), "+f"(c[1]), "+f"(c[2]), "+f"(c[3])
        : "r"(a[0]), "r"(a[1]), "r"(a[2]), "r"(a[3]), "r"(b[0]), "r"(b[1]));
}

// Stage tile geometry: 128 rows x 64 bf16 cols, padded to 72 elem (144 B)
#define ATILE 18432
#define ABUF  73728    // 4 tiles (Ahi, Alo, Bhi, Blo)

// Load one stage (512 threads): 4 tiles of [128 x 64] bf16, row-major sources.
__device__ __forceinline__ void load_stage4(
    uint32_t sb, uint32_t bufo, int tid,
    const __nv_bfloat16* A0, const __nv_bfloat16* A1,
    const __nv_bfloat16* B0, const __nv_bfloat16* B1,
    int arow0, int brow0, int dk)
{
    #pragma unroll
    for (int i = 0; i < 2; i++) {
        const int idx = i * 512 + tid;
        const int row = idx >> 3;
        const int c   = idx & 7;
        const uint32_t so = sb + bufo + row * 144 + c * 16;
        const size_t ga = (size_t)(arow0 + row) * DMODEL + dk + c * 8;
        const size_t gb = (size_t)(brow0 + row) * DMODEL + dk + c * 8;
        cpa16(so,             A0 + ga);
        cpa16(so + ATILE,     A1 + ga);
        cpa16(so + 2 * ATILE, B0 + gb);
        cpa16(so + 3 * ATILE, B1 + gb);
    }
    CP_COMMIT();
}

// One K=64 compute stage, 4x4 warp grid, 32x32 warp tile, 3-term split.
__device__ __forceinline__ void mma_stage(
    float C[2][4][4], uint32_t sb, uint32_t bufo, int l, int wy, int wx)
{
    #pragma unroll
    for (int kk = 0; kk < 4; kk++) {
        uint32_t ah[2][4], al[2][4];
        #pragma unroll
        for (int mi = 0; mi < 2; mi++) {
            const uint32_t ra = sb + bufo
                + (uint32_t)(wy * 32 + mi * 16 + (l & 15)) * 144
                + (uint32_t)(kk * 16 + ((l >> 4) << 3)) * 2;
            ldsm_x4(ah[mi], ra);
            ldsm_x4(al[mi], ra + ATILE);
        }
        #pragma unroll
        for (int ni = 0; ni < 4; ni++) {
            const uint32_t rb = sb + bufo + 2 * ATILE
                + (uint32_t)(wx * 32 + ni * 8 + (l & 7)) * 144
                + (uint32_t)(kk * 16 + (((l >> 3) & 1) << 3)) * 2;
            uint32_t bh[2], bl[2];
            ldsm_x2(bh, rb);
            ldsm_x2(bl, rb + ATILE);
            #pragma unroll
            for (int mi = 0; mi < 2; mi++) {
                mma_bf16(C[mi][ni], ah[mi], bh);
                mma_bf16(C[mi][ni], ah[mi], bl);
                mma_bf16(C[mi][ni], al[mi], bh);
            }
        }
    }
}

// ===========================================================================
// Convert kernels
// ===========================================================================
__global__ __launch_bounds__(256) void split_x_kernel(const float* __restrict__ X) {
    const int i = blockIdx.x * 256 + threadIdx.x;   // over float4s
    float4 v = ((const float4*)X)[i];
    __nv_bfloat16 h0 = __float2bfloat16(v.x);
    __nv_bfloat16 h1 = __float2bfloat16(v.y);
    __nv_bfloat16 h2 = __float2bfloat16(v.z);
    __nv_bfloat16 h3 = __float2bfloat16(v.w);
    __nv_bfloat16 l0 = __float2bfloat16(v.x - __bfloat162float(h0));
    __nv_bfloat16 l1 = __float2bfloat16(v.y - __bfloat162float(h1));
    __nv_bfloat16 l2 = __float2bfloat16(v.z - __bfloat162float(h2));
    __nv_bfloat16 l3 = __float2bfloat16(v.w - __bfloat162float(h3));
    ((__nv_bfloat162*)g_Xhi)[i * 2 + 0] = __nv_bfloat162(h0, h1);
    ((__nv_bfloat162*)g_Xhi)[i * 2 + 1] = __nv_bfloat162(h2, h3);
    ((__nv_bfloat162*)g_Xlo)[i * 2 + 0] = __nv_bfloat162(l0, l1);
    ((__nv_bfloat162*)g_Xlo)[i * 2 + 1] = __nv_bfloat162(l2, l3);
}

__global__ void splitT_w_kernel(const float* __restrict__ Wq,
                                const float* __restrict__ Wk,
                                const float* __restrict__ Wv) {
    __shared__ float t[32][33];
    const int z = blockIdx.z;
    const float* W = (z == 0) ? Wq : (z == 1) ? Wk : Wv;
    const int k = blockIdx.y * 32 + threadIdx.y;
    const int n = blockIdx.x * 32 + threadIdx.x;
    t[threadIdx.y][threadIdx.x] = W[k * DMODEL + n];
    __syncthreads();
    const int on = blockIdx.x * 32 + threadIdx.y;   // output row (n)
    const int ok = blockIdx.y * 32 + threadIdx.x;   // output col (k)
    float v = t[threadIdx.x][threadIdx.y];
    __nv_bfloat16 h = __float2bfloat16(v);
    __nv_bfloat16 l = __float2bfloat16(v - __bfloat162float(h));
    g_Wthi[(size_t)z * DMODEL * DMODEL + on * DMODEL + ok] = h;
    g_Wtlo[(size_t)z * DMODEL * DMODEL + on * DMODEL + ok] = l;
}

// ===========================================================================
// QKV projection: out = X @ W + b, written as hi/lo bf16 pairs.
// grid (8, 128, 3), 512 threads, warp grid 4x4 (wy m32, wx n32).
// ===========================================================================
#define PROJ_SMEM (2 * ABUF)

__global__ __launch_bounds__(512) void qkv_mma_kernel(
    const float* __restrict__ bq, const float* __restrict__ bk,
    const float* __restrict__ bv)
{
    extern __shared__ char smc[];
    const uint32_t sb = smem_to_u32(smc);
    const int tid = threadIdx.x;
    const int l = tid & 31, w = tid >> 5;
    const int wy = w >> 2, wx = w & 3;
    const int z = blockIdx.z, m0 = blockIdx.y * 128, n0 = blockIdx.x * 128;

    const __nv_bfloat16* Bh = g_Wthi + (size_t)z * DMODEL * DMODEL;
    const __nv_bfloat16* Bl = g_Wtlo + (size_t)z * DMODEL * DMODEL;
    const float* bias = (z == 0) ? bq : (z == 1) ? bk : bv;
    __nv_bfloat16* ohi = (z == 0) ? g_Qhi : (z == 1) ? g_Khi : g_Vhi;
    __nv_bfloat16* olo = (z == 0) ? g_Qlo : (z == 1) ? g_Klo : g_Vlo;

    float C[2][4][4];
    #pragma unroll
    for (int mi = 0; mi < 2; mi++)
        #pragma unroll
        for (int ni = 0; ni < 4; ni++)
            #pragma unroll
            for (int q = 0; q < 4; q++) C[mi][ni][q] = 0.f;

    load_stage4(sb, 0, tid, g_Xhi, g_Xlo, Bh, Bl, m0, n0, 0);
    for (int kc = 0; kc < 16; kc++) {
        if (kc + 1 < 16) {
            load_stage4(sb, ((kc + 1) & 1) * ABUF, tid, g_Xhi, g_Xlo, Bh, Bl,
                        m0, n0, (kc + 1) * 64);
            CP_WAIT(1);
        } else {
            CP_WAIT(0);
        }
        __syncthreads();
        mma_stage(C, sb, (kc & 1) * ABUF, l, wy, wx);
        __syncthreads();
    }

    // epilogue: bias add + hi/lo split store
    #pragma unroll
    for (int mi = 0; mi < 2; mi++)
        #pragma unroll
        for (int ni = 0; ni < 4; ni++)
            #pragma unroll
            for (int h = 0; h < 2; h++) {
                const int r = m0 + wy * 32 + mi * 16 + h * 8 + (l >> 2);
                const int c = n0 + wx * 32 + ni * 8 + 2 * (l & 3);
                const float v0 = C[mi][ni][2 * h + 0] + bias[c];
                const float v1 = C[mi][ni][2 * h + 1] + bias[c + 1];
                const __nv_bfloat16 h0 = __float2bfloat16(v0);
                const __nv_bfloat16 h1 = __float2bfloat16(v1);
                const __nv_bfloat16 l0 = __float2bfloat16(v0 - __bfloat162float(h0));
                const __nv_bfloat16 l1 = __float2bfloat16(v1 - __bfloat162float(h1));
                *(__nv_bfloat162*)&ohi[(size_t)r * DMODEL + c] = __nv_bfloat162(h0, h1);
                *(__nv_bfloat162*)&olo[(size_t)r * DMODEL + c] = __nv_bfloat162(l0, l1);
            }
}

// ===========================================================================
// Attention: flash-style with mma.sync for S and PV.
// grid (16, 8), 512 threads, warp grid 4x4, warp tile 32x32.
// ===========================================================================
#define PTILEB   34816          // 128 x 136 bf16 (272 B rows)
#define VBUF     69632          // Vhi + Vlo, one stage
#define OFF_P    147456
#define OFF_PLO  (OFF_P + PTILEB)
#define OFF_PMAX (OFF_P + 2 * PTILEB)        // float[4][128]
#define OFF_PSUM (OFF_PMAX + 2048)           // float[4][128]
#define OFF_MS   (OFF_PSUM + 2048)           // float[128]
#define OFF_LS   (OFF_MS + 512)              // float[128]
#define ATTN_SMEM 222208

__global__ __launch_bounds__(512) void attn_mma_kernel(float* __restrict__ Out)
{
    extern __shared__ char smc[];
    const uint32_t sb = smem_to_u32(smc);
    float* pmax = (float*)(smc + OFF_PMAX);
    float* psum = (float*)(smc + OFF_PSUM);
    float* m_s  = (float*)(smc + OFF_MS);
    float* l_s  = (float*)(smc + OFF_LS);

    const int tid = threadIdx.x;
    const int l = tid & 31, w = tid >> 5;
    const int wy = w >> 2, wx = w & 3;
    const int b = blockIdx.y, qt = blockIdx.x;
    const int q0 = b * SEQ + qt * 128;
    const int kb = b * SEQ;

    if (tid < 128) {
        m_s[tid] = __int_as_float(0xff800000);
        l_s[tid] = 0.f;
    }
    __syncthreads();

    for (int kt = 0; kt < 16; kt++) {
        const int k0 = kb + kt * 128;

        // ================= S = Q K^T (split-bf16 mma) =================
        float C[2][4][4];
        #pragma unroll
        for (int mi = 0; mi < 2; mi++)
            #pragma unroll
            for (int ni = 0; ni < 4; ni++)
                #pragma unroll
                for (int q = 0; q < 4; q++) C[mi][ni][q] = 0.f;

        load_stage4(sb, 0, tid, g_Qhi, g_Qlo, g_Khi, g_Klo, q0, k0, 0);
        for (int s = 0; s < 16; s++) {
            if (s + 1 < 16) {
                load_stage4(sb, ((s + 1) & 1) * ABUF, tid, g_Qhi, g_Qlo,
                            g_Khi, g_Klo, q0, k0, (s + 1) * 64);
                CP_WAIT(1);
            } else {
                CP_WAIT(0);
            }
            __syncthreads();
            mma_stage(C, sb, (s & 1) * ABUF, l, wy, wx);
            __syncthreads();
        }

        // prefetch V chunk 0
        {
            #pragma unroll
            for (int i = 0; i < 4; i++) {
                const int idx = i * 512 + tid;
                const int row = idx >> 4, c = idx & 15;
                const uint32_t dst = sb + (uint32_t)(row * 272 + c * 16);
                const size_t g = (size_t)(k0 + row) * DMODEL + c * 8;
                cpa16(dst, g_Vhi + g);
                cpa16(dst + PTILEB, g_Vlo + g);
            }
            CP_COMMIT();
        }

        // ================= online softmax =================
        #pragma unroll
        for (int mi = 0; mi < 2; mi++)
            #pragma unroll
            for (int h = 0; h < 2; h++) {
                float m = __int_as_float(0xff800000);
                #pragma unroll
                for (int ni = 0; ni < 4; ni++)
                    m = fmaxf(m, fmaxf(C[mi][ni][2 * h], C[mi][ni][2 * h + 1]));
                m = fmaxf(m, __shfl_xor_sync(0xffffffffu, m, 1));
                m = fmaxf(m, __shfl_xor_sync(0xffffffffu, m, 2));
                if ((l & 3) == 0)
                    pmax[wx * 128 + wy * 32 + mi * 16 + h * 8 + (l >> 2)] = m;
            }
        __syncthreads();

        float alpha[4], mnew[4];
        #pragma unroll
        for (int mi = 0; mi < 2; mi++)
            #pragma unroll
            for (int h = 0; h < 2; h++) {
                const int sl = mi * 2 + h;
                const int row = wy * 32 + mi * 16 + h * 8 + (l >> 2);
                const float mo = m_s[row];
                float mx = fmaxf(fmaxf(pmax[row], pmax[128 + row]),
                                 fmaxf(pmax[256 + row], pmax[384 + row]));
                const float mn = fmaxf(mo, mx);
                mnew[sl] = mn;
                alpha[sl] = __expf(mo - mn);
                float ssum = 0.f;
                #pragma unroll
                for (int ni = 0; ni < 4; ni++) {
                    float e0 = __expf(C[mi][ni][2 * h] - mn);
                    float e1 = __expf(C[mi][ni][2 * h + 1] - mn);
                    ssum += e0 + e1;
                    const int col = wx * 32 + ni * 8 + 2 * (l & 3);
                    const __nv_bfloat16 p0h = __float2bfloat16(e0);
                    const __nv_bfloat16 p1h = __float2bfloat16(e1);
                    const __nv_bfloat16 p0l = __float2bfloat16(e0 - __bfloat162float(p0h));
                    const __nv_bfloat16 p1l = __float2bfloat16(e1 - __bfloat162float(p1h));
                    *(__nv_bfloat162*)(smc + OFF_P   + row * 272 + col * 2) = __nv_bfloat162(p0h, p1h);
                    *(__nv_bfloat162*)(smc + OFF_PLO + row * 272 + col * 2) = __nv_bfloat162(p0l, p1l);
                }
                ssum += __shfl_xor_sync(0xffffffffu, ssum, 1);
                ssum += __shfl_xor_sync(0xffffffffu, ssum, 2);
                if ((l & 3) == 0) psum[wx * 128 + row] = ssum;
            }
        __syncthreads();

        if (wx == 0 && (l & 3) == 0) {
            #pragma unroll
            for (int mi = 0; mi < 2; mi++)
                #pragma unroll
                for (int h = 0; h < 2; h++) {
                    const int sl = mi * 2 + h;
                    const int row = wy * 32 + mi * 16 + h * 8 + (l >> 2);
                    const float ss = psum[row] + psum[128 + row] +
                                     psum[256 + row] + psum[384 + row];
                    l_s[row] = l_s[row] * alpha[sl] + ss;
                    m_s[row] = mnew[sl];
                }
        }
        __syncthreads();

        // ================= O += P V (split-bf16 mma) =================
        const bool first = (kt == 0);
        const bool last  = (kt == 15);

        for (int nc = 0; nc < 8; nc++) {
            if (nc + 1 < 8) {
                const uint32_t slot = ((nc + 1) & 1) * VBUF;
                #pragma unroll
                for (int i = 0; i < 4; i++) {
                    const int idx = i * 512 + tid;
                    const int row = idx >> 4, c = idx & 15;
                    const uint32_t dst = sb + slot + (uint32_t)(row * 272 + c * 16);
                    const size_t g = (size_t)(k0 + row) * DMODEL + (nc + 1) * 128 + c * 8;
                    cpa16(dst, g_Vhi + g);
                    cpa16(dst + PTILEB, g_Vlo + g);
                }
                CP_COMMIT();
                CP_WAIT(1);
            } else {
                CP_WAIT(0);
            }
            __syncthreads();

            float Oc[2][4][4];
            if (first) {
                #pragma unroll
                for (int mi = 0; mi < 2; mi++)
                    #pragma unroll
                    for (int ni = 0; ni < 4; ni++)
                        #pragma unroll
                        for (int q = 0; q < 4; q++) Oc[mi][ni][q] = 0.f;
            } else {
                #pragma unroll
                for (int mi = 0; mi < 2; mi++)
                    #pragma unroll
                    for (int ni = 0; ni < 4; ni++)
                        #pragma unroll
                        for (int h = 0; h < 2; h++) {
                            const int r = wy * 32 + mi * 16 + h * 8 + (l >> 2);
                            const int c = nc * 128 + wx * 32 + ni * 8 + 2 * (l & 3);
                            const float2 p = *(const float2*)&Out[(size_t)(q0 + r) * DMODEL + c];
                            Oc[mi][ni][2 * h]     = p.x * alpha[mi * 2 + h];
                            Oc[mi][ni][2 * h + 1] = p.y * alpha[mi * 2 + h];
                        }
            }

            const uint32_t slot = (nc & 1) * VBUF;
            #pragma unroll
            for (int kk = 0; kk < 8; kk++) {
                uint32_t ph[2][4], pl[2][4];
                #pragma unroll
                for (int mi = 0; mi < 2; mi++) {
                    const uint32_t ra = sb + OFF_P
                        + (uint32_t)(wy * 32 + mi * 16 + (l & 15)) * 272
                        + (uint32_t)(kk * 16 + ((l >> 4) << 3)) * 2;
                    ldsm_x4(ph[mi], ra);
                    ldsm_x4(pl[mi], ra + PTILEB);
                }
                #pragma unroll
                for (int ni = 0; ni < 4; ni++) {
                    const uint32_t rb = sb + slot
                        + (uint32_t)(kk * 16 + (l & 15)) * 272
                        + (uint32_t)(wx * 32 + ni * 8) * 2;
                    uint32_t vh[2], vl[2];
                    ldsm_x2t(vh, rb);
                    ldsm_x2t(vl, rb + PTILEB);
                    #pragma unroll
                    for (int mi = 0; mi < 2; mi++) {
                        mma_bf16(Oc[mi][ni], ph[mi], vh);
                        mma_bf16(Oc[mi][ni], ph[mi], vl);
                        mma_bf16(Oc[mi][ni], pl[mi], vh);
                    }
                }
            }

            // store O chunk
            #pragma unroll
            for (int mi = 0; mi < 2; mi++)
                #pragma unroll
                for (int ni = 0; ni < 4; ni++)
                    #pragma unroll
                    for (int h = 0; h < 2; h++) {
                        const int r = wy * 32 + mi * 16 + h * 8 + (l >> 2);
                        const int c = nc * 128 + wx * 32 + ni * 8 + 2 * (l & 3);
                        const float sc = last ? (1.f / l_s[r]) : 1.f;
                        float2 p;
                        p.x = Oc[mi][ni][2 * h] * sc;
                        p.y = Oc[mi][ni][2 * h + 1] * sc;
                        *(float2*)&Out[(size_t)(q0 + r) * DMODEL + c] = p;
                    }
            __syncthreads();
        }
    }
}

// ---------------------------------------------------------------------------
extern "C" void kernel_launch(void* const* d_in, const int* in_sizes, int n_in,
                              void* d_out, int out_size)
{
    const float* X  = (const float*)d_in[0];
    const float* Wq = (const float*)d_in[1];
    const float* bq = (const float*)d_in[2];
    const float* Wk = (const float*)d_in[3];
    const float* bk = (const float*)d_in[4];
    const float* Wv = (const float*)d_in[5];
    const float* bv = (const float*)d_in[6];
    float* Out = (float*)d_out;

    split_x_kernel<<<NTOK * DMODEL / 4 / 256, 256>>>(X);
    splitT_w_kernel<<<dim3(32, 32, 3), dim3(32, 32)>>>(Wq, Wk, Wv);

    cudaFuncSetAttribute(qkv_mma_kernel, cudaFuncAttributeMaxDynamicSharedMemorySize, PROJ_SMEM);
    qkv_mma_kernel<<<dim3(DMODEL / 128, NTOK / 128, 3), 512, PROJ_SMEM>>>(bq, bk, bv);

    cudaFuncSetAttribute(attn_mma_kernel, cudaFuncAttributeMaxDynamicSharedMemorySize, ATTN_SMEM);
    attn_mma_kernel<<<dim3(SEQ / 128, NBATCH), 512, ATTN_SMEM>>>(Out);
}

// round 6
// speedup vs baseline: 1.2219x; 1.2219x over previous
#include <cuda_runtime.h>
#include <cuda_bf16.h>
#include <cstdint>
#include <math.h>

// Problem constants
#define DMODEL 1024
#define NBATCH 8
#define SEQ    2048
#define NTOK   (NBATCH * SEQ)   // 16384

// split-bf16 global scratch
__device__ __nv_bfloat16 g_Xhi[NTOK * DMODEL];
__device__ __nv_bfloat16 g_Xlo[NTOK * DMODEL];
__device__ __nv_bfloat16 g_Wthi[3 * DMODEL * DMODEL];  // W^T, [z][n][k]
__device__ __nv_bfloat16 g_Wtlo[3 * DMODEL * DMODEL];
__device__ __nv_bfloat16 g_Qhi[NTOK * DMODEL];
__device__ __nv_bfloat16 g_Qlo[NTOK * DMODEL];
__device__ __nv_bfloat16 g_Khi[NTOK * DMODEL];
__device__ __nv_bfloat16 g_Klo[NTOK * DMODEL];
__device__ __nv_bfloat16 g_Vhi[NTOK * DMODEL];
__device__ __nv_bfloat16 g_Vlo[NTOK * DMODEL];
// attention intermediates
__device__ float         g_S[(size_t)NTOK * SEQ];     // scores, 134 MB
__device__ __nv_bfloat16 g_Phi[(size_t)NTOK * SEQ];   // exp(S-m), hi
__device__ __nv_bfloat16 g_Plo[(size_t)NTOK * SEQ];   // exp(S-m), lo
__device__ float         g_l[NTOK];                   // row sums

// ===========================================================================
// helpers
// ===========================================================================
__device__ __forceinline__ uint32_t smem_to_u32(const void* p) {
    uint32_t a;
    asm("{ .reg .u64 t; cvta.to.shared.u64 t, %1; cvt.u32.u64 %0, t; }" : "=r"(a) : "l"(p));
    return a;
}
__device__ __forceinline__ void cpa16(uint32_t d, const void* s) {
    asm volatile("cp.async.cg.shared.global [%0], [%1], 16;" :: "r"(d), "l"(s));
}
#define CP_COMMIT() asm volatile("cp.async.commit_group;")
#define CP_WAIT(N)  asm volatile("cp.async.wait_group %0;" :: "n"(N))

__device__ __forceinline__ void ldsm_x4(uint32_t r[4], uint32_t a) {
    asm volatile("ldmatrix.sync.aligned.m8n8.x4.shared.b16 {%0,%1,%2,%3}, [%4];"
        : "=r"(r[0]), "=r"(r[1]), "=r"(r[2]), "=r"(r[3]) : "r"(a));
}
__device__ __forceinline__ void ldsm_x2(uint32_t r[2], uint32_t a) {
    asm volatile("ldmatrix.sync.aligned.m8n8.x2.shared.b16 {%0,%1}, [%2];"
        : "=r"(r[0]), "=r"(r[1]) : "r"(a));
}
__device__ __forceinline__ void ldsm_x2t(uint32_t r[2], uint32_t a) {
    asm volatile("ldmatrix.sync.aligned.m8n8.x2.trans.shared.b16 {%0,%1}, [%2];"
        : "=r"(r[0]), "=r"(r[1]) : "r"(a));
}
__device__ __forceinline__ void mma_bf16(float c[4], const uint32_t a[4], const uint32_t b[2]) {
    asm volatile("mma.sync.aligned.m16n8k16.row.col.f32.bf16.bf16.f32 "
        "{%0,%1,%2,%3}, {%4,%5,%6,%7}, {%8,%9}, {%0,%1,%2,%3};"
        : "+f"(c[0]), "+f"(c[1]), "+f"(c[2]), "+f"(c[3])
        : "r"(a[0]), "r"(a[1]), "r"(a[2]), "r"(a[3]), "r"(b[0]), "r"(b[1]));
}

// Stage tile geometry (A/B both 128 rows x 64 bf16 cols, padded to 144 B)
#define ATILE 18432
#define ABUF  73728             // 4 tiles (Ahi, Alo, Bhi, Blo)
#define SMEM3 (3 * ABUF)        // 221184

// Load one stage (256 threads): A/B row-major, k-contiguous, stride ld.
__device__ __forceinline__ void load_stageAB(
    uint32_t sb, uint32_t bufo, int tid,
    const __nv_bfloat16* A0, const __nv_bfloat16* A1,
    const __nv_bfloat16* B0, const __nv_bfloat16* B1,
    int ld, int arow0, int brow0, int dk)
{
    #pragma unroll
    for (int i = 0; i < 4; i++) {
        const int idx = i * 256 + tid;
        const int row = idx >> 3;
        const int c   = idx & 7;
        const uint32_t so = sb + bufo + row * 144 + c * 16;
        const size_t ga = (size_t)(arow0 + row) * ld + dk + c * 8;
        const size_t gb = (size_t)(brow0 + row) * ld + dk + c * 8;
        cpa16(so,             A0 + ga);
        cpa16(so + ATILE,     A1 + ga);
        cpa16(so + 2 * ATILE, B0 + gb);
        cpa16(so + 3 * ATILE, B1 + gb);
    }
    CP_COMMIT();
}

// One K=64 compute stage, warp grid 2x4, warp tile 64x32, 3-term split.
__device__ __forceinline__ void mma_stage(
    float C[4][4][4], uint32_t sb, uint32_t bufo, int l, int wy, int wx)
{
    #pragma unroll
    for (int kk = 0; kk < 4; kk++) {
        uint32_t ah[4][4], al[4][4];
        #pragma unroll
        for (int mi = 0; mi < 4; mi++) {
            const uint32_t ra = sb + bufo
                + (uint32_t)(wy * 64 + mi * 16 + (l & 15)) * 144
                + (uint32_t)(kk * 16 + ((l >> 4) << 3)) * 2;
            ldsm_x4(ah[mi], ra);
            ldsm_x4(al[mi], ra + ATILE);
        }
        #pragma unroll
        for (int ni = 0; ni < 4; ni++) {
            const uint32_t rb = sb + bufo + 2 * ATILE
                + (uint32_t)(wx * 32 + ni * 8 + (l & 7)) * 144
                + (uint32_t)(kk * 16 + (((l >> 3) & 1) << 3)) * 2;
            uint32_t bh[2], bl[2];
            ldsm_x2(bh, rb);
            ldsm_x2(bl, rb + ATILE);
            #pragma unroll
            for (int mi = 0; mi < 4; mi++) {
                mma_bf16(C[mi][ni], ah[mi], bh);
                mma_bf16(C[mi][ni], ah[mi], bl);
                mma_bf16(C[mi][ni], al[mi], bh);
            }
        }
    }
}

// ===========================================================================
// Convert kernels
// ===========================================================================
__global__ __launch_bounds__(256) void split_x_kernel(const float* __restrict__ X) {
    const int i = blockIdx.x * 256 + threadIdx.x;   // over float4s
    float4 v = ((const float4*)X)[i];
    __nv_bfloat16 h0 = __float2bfloat16(v.x);
    __nv_bfloat16 h1 = __float2bfloat16(v.y);
    __nv_bfloat16 h2 = __float2bfloat16(v.z);
    __nv_bfloat16 h3 = __float2bfloat16(v.w);
    __nv_bfloat16 l0 = __float2bfloat16(v.x - __bfloat162float(h0));
    __nv_bfloat16 l1 = __float2bfloat16(v.y - __bfloat162float(h1));
    __nv_bfloat16 l2 = __float2bfloat16(v.z - __bfloat162float(h2));
    __nv_bfloat16 l3 = __float2bfloat16(v.w - __bfloat162float(h3));
    ((__nv_bfloat162*)g_Xhi)[i * 2 + 0] = __nv_bfloat162(h0, h1);
    ((__nv_bfloat162*)g_Xhi)[i * 2 + 1] = __nv_bfloat162(h2, h3);
    ((__nv_bfloat162*)g_Xlo)[i * 2 + 0] = __nv_bfloat162(l0, l1);
    ((__nv_bfloat162*)g_Xlo)[i * 2 + 1] = __nv_bfloat162(l2, l3);
}

__global__ void splitT_w_kernel(const float* __restrict__ Wq,
                                const float* __restrict__ Wk,
                                const float* __restrict__ Wv) {
    __shared__ float t[32][33];
    const int z = blockIdx.z;
    const float* W = (z == 0) ? Wq : (z == 1) ? Wk : Wv;
    const int k = blockIdx.y * 32 + threadIdx.y;
    const int n = blockIdx.x * 32 + threadIdx.x;
    t[threadIdx.y][threadIdx.x] = W[k * DMODEL + n];
    __syncthreads();
    const int on = blockIdx.x * 32 + threadIdx.y;   // output row (n)
    const int ok = blockIdx.y * 32 + threadIdx.x;   // output col (k)
    float v = t[threadIdx.x][threadIdx.y];
    __nv_bfloat16 h = __float2bfloat16(v);
    __nv_bfloat16 l = __float2bfloat16(v - __bfloat162float(h));
    g_Wthi[(size_t)z * DMODEL * DMODEL + on * DMODEL + ok] = h;
    g_Wtlo[(size_t)z * DMODEL * DMODEL + on * DMODEL + ok] = l;
}

// ===========================================================================
// Kernel 1: QKV projection (3-stage pipeline). grid (8, 128, 3), 256 thr.
// ===========================================================================
__global__ __launch_bounds__(256) void qkv_mma_kernel(
    const float* __restrict__ bq, const float* __restrict__ bk,
    const float* __restrict__ bv)
{
    extern __shared__ char smc[];
    const uint32_t sb = smem_to_u32(smc);
    const int tid = threadIdx.x;
    const int l = tid & 31, w = tid >> 5;
    const int wy = w >> 2, wx = w & 3;
    const int z = blockIdx.z, m0 = blockIdx.y * 128, n0 = blockIdx.x * 128;

    const __nv_bfloat16* Bh = g_Wthi + (size_t)z * DMODEL * DMODEL;
    const __nv_bfloat16* Bl = g_Wtlo + (size_t)z * DMODEL * DMODEL;
    const float* bias = (z == 0) ? bq : (z == 1) ? bk : bv;
    __nv_bfloat16* ohi = (z == 0) ? g_Qhi : (z == 1) ? g_Khi : g_Vhi;
    __nv_bfloat16* olo = (z == 0) ? g_Qlo : (z == 1) ? g_Klo : g_Vlo;

    float C[4][4][4];
    #pragma unroll
    for (int mi = 0; mi < 4; mi++)
        #pragma unroll
        for (int ni = 0; ni < 4; ni++)
            #pragma unroll
            for (int q = 0; q < 4; q++) C[mi][ni][q] = 0.f;

    load_stageAB(sb, 0,    tid, g_Xhi, g_Xlo, Bh, Bl, DMODEL, m0, n0, 0);
    load_stageAB(sb, ABUF, tid, g_Xhi, g_Xlo, Bh, Bl, DMODEL, m0, n0, 64);
    for (int kc = 0; kc < 16; kc++) {
        if (kc + 1 < 16) { CP_WAIT(1); } else { CP_WAIT(0); }
        __syncthreads();
        if (kc + 2 < 16)
            load_stageAB(sb, ((kc + 2) % 3) * ABUF, tid, g_Xhi, g_Xlo, Bh, Bl,
                         DMODEL, m0, n0, (kc + 2) * 64);
        mma_stage(C, sb, (kc % 3) * ABUF, l, wy, wx);
    }

    // epilogue: bias add + hi/lo split store
    #pragma unroll
    for (int mi = 0; mi < 4; mi++)
        #pragma unroll
        for (int ni = 0; ni < 4; ni++)
            #pragma unroll
            for (int h = 0; h < 2; h++) {
                const int r = m0 + wy * 64 + mi * 16 + h * 8 + (l >> 2);
                const int c = n0 + wx * 32 + ni * 8 + 2 * (l & 3);
                const float v0 = C[mi][ni][2 * h + 0] + bias[c];
                const float v1 = C[mi][ni][2 * h + 1] + bias[c + 1];
                const __nv_bfloat16 h0 = __float2bfloat16(v0);
                const __nv_bfloat16 h1 = __float2bfloat16(v1);
                const __nv_bfloat16 l0 = __float2bfloat16(v0 - __bfloat162float(h0));
                const __nv_bfloat16 l1 = __float2bfloat16(v1 - __bfloat162float(h1));
                *(__nv_bfloat162*)&ohi[(size_t)r * DMODEL + c] = __nv_bfloat162(h0, h1);
                *(__nv_bfloat162*)&olo[(size_t)r * DMODEL + c] = __nv_bfloat162(l0, l1);
            }
}

// ===========================================================================
// Kernel 2: S = Q K^T (per batch). grid (16 k-tiles, 128 q-tiles), 256 thr.
// ===========================================================================
__global__ __launch_bounds__(256) void sgemm_kernel()
{
    extern __shared__ char smc[];
    const uint32_t sb = smem_to_u32(smc);
    const int tid = threadIdx.x;
    const int l = tid & 31, w = tid >> 5;
    const int wy = w >> 2, wx = w & 3;
    const int q0 = blockIdx.y * 128;              // global query row
    const int b  = q0 >> 11;                      // /2048
    const int k0 = b * SEQ + blockIdx.x * 128;    // global key row

    float C[4][4][4];
    #pragma unroll
    for (int mi = 0; mi < 4; mi++)
        #pragma unroll
        for (int ni = 0; ni < 4; ni++)
            #pragma unroll
            for (int q = 0; q < 4; q++) C[mi][ni][q] = 0.f;

    load_stageAB(sb, 0,    tid, g_Qhi, g_Qlo, g_Khi, g_Klo, DMODEL, q0, k0, 0);
    load_stageAB(sb, ABUF, tid, g_Qhi, g_Qlo, g_Khi, g_Klo, DMODEL, q0, k0, 64);
    for (int kc = 0; kc < 16; kc++) {
        if (kc + 1 < 16) { CP_WAIT(1); } else { CP_WAIT(0); }
        __syncthreads();
        if (kc + 2 < 16)
            load_stageAB(sb, ((kc + 2) % 3) * ABUF, tid, g_Qhi, g_Qlo,
                         g_Khi, g_Klo, DMODEL, q0, k0, (kc + 2) * 64);
        mma_stage(C, sb, (kc % 3) * ABUF, l, wy, wx);
    }

    // epilogue: store scores fp32
    #pragma unroll
    for (int mi = 0; mi < 4; mi++)
        #pragma unroll
        for (int ni = 0; ni < 4; ni++)
            #pragma unroll
            for (int h = 0; h < 2; h++) {
                const int r = q0 + wy * 64 + mi * 16 + h * 8 + (l >> 2);
                const int c = blockIdx.x * 128 + wx * 32 + ni * 8 + 2 * (l & 3);
                float2 s;
                s.x = C[mi][ni][2 * h + 0];
                s.y = C[mi][ni][2 * h + 1];
                *(float2*)&g_S[(size_t)r * SEQ + c] = s;
            }
}

// ===========================================================================
// Kernel 3: softmax rows. grid 16384, 256 thr. Writes unnormalized
// P = exp(S - rowmax) as bf16 hi/lo, and row sum l.
// ===========================================================================
__global__ __launch_bounds__(256) void softmax_kernel()
{
    __shared__ float red[8];
    const int tid = threadIdx.x;
    const int lane = tid & 31, wrp = tid >> 5;
    const size_t row = blockIdx.x;
    const float* Sr = g_S + row * SEQ;

    float4 v0 = ((const float4*)Sr)[tid];
    float4 v1 = ((const float4*)Sr)[tid + 256];

    float m = fmaxf(fmaxf(fmaxf(v0.x, v0.y), fmaxf(v0.z, v0.w)),
                    fmaxf(fmaxf(v1.x, v1.y), fmaxf(v1.z, v1.w)));
    #pragma unroll
    for (int off = 16; off >= 1; off >>= 1)
        m = fmaxf(m, __shfl_xor_sync(0xffffffffu, m, off));
    if (lane == 0) red[wrp] = m;
    __syncthreads();
    float mm = red[0];
    #pragma unroll
    for (int i = 1; i < 8; i++) mm = fmaxf(mm, red[i]);
    __syncthreads();

    float e[8];
    e[0] = __expf(v0.x - mm); e[1] = __expf(v0.y - mm);
    e[2] = __expf(v0.z - mm); e[3] = __expf(v0.w - mm);
    e[4] = __expf(v1.x - mm); e[5] = __expf(v1.y - mm);
    e[6] = __expf(v1.z - mm); e[7] = __expf(v1.w - mm);

    float s = 0.f;
    #pragma unroll
    for (int i = 0; i < 8; i++) s += e[i];
    #pragma unroll
    for (int off = 16; off >= 1; off >>= 1)
        s += __shfl_xor_sync(0xffffffffu, s, off);
    if (lane == 0) red[wrp] = s;
    __syncthreads();
    if (tid == 0) {
        float tot = 0.f;
        #pragma unroll
        for (int i = 0; i < 8; i++) tot += red[i];
        g_l[row] = tot;
    }

    // write P hi/lo
    #pragma unroll
    for (int half = 0; half < 2; half++) {
        const size_t base = row * SEQ + (half * 256 + tid) * 4;
        #pragma unroll
        for (int j = 0; j < 2; j++) {
            const float a = e[half * 4 + 2 * j], bb = e[half * 4 + 2 * j + 1];
            const __nv_bfloat16 ah = __float2bfloat16(a);
            const __nv_bfloat16 bh = __float2bfloat16(bb);
            const __nv_bfloat16 al = __float2bfloat16(a - __bfloat162float(ah));
            const __nv_bfloat16 bl = __float2bfloat16(bb - __bfloat162float(bh));
            *(__nv_bfloat162*)&g_Phi[base + 2 * j] = __nv_bfloat162(ah, bh);
            *(__nv_bfloat162*)&g_Plo[base + 2 * j] = __nv_bfloat162(al, bl);
        }
    }
}

// ===========================================================================
// Kernel 4: O = (P V) / l. grid (8 d-tiles, 128 q-tiles), 256 thr.
// K depth = 2048 tokens, 32 stages of 64. O in registers.
// ===========================================================================
#define PV_AT 18432                          // P half-tile: 128 x 144 B
#define PV_BT 17408                          // V half-tile: 64 x 272 B
#define PV_STAGE (2 * PV_AT + 2 * PV_BT)     // 71680
#define PV_SMEM (3 * PV_STAGE)               // 215040

__device__ __forceinline__ void load_pv_stage(
    uint32_t sb, uint32_t bufo, int tid, int q0, int kb, int d0, int s)
{
    #pragma unroll
    for (int i = 0; i < 4; i++) {            // P tiles: 128 rows x 64 cols
        const int idx = i * 256 + tid;
        const int row = idx >> 3;
        const int c   = idx & 7;
        const uint32_t so = sb + bufo + row * 144 + c * 16;
        const size_t g = (size_t)(q0 + row) * SEQ + s * 64 + c * 8;
        cpa16(so,         g_Phi + g);
        cpa16(so + PV_AT, g_Plo + g);
    }
    #pragma unroll
    for (int i = 0; i < 4; i++) {            // V tiles: 64 rows x 128 cols
        const int idx = i * 256 + tid;
        const int row = idx >> 4;
        const int c   = idx & 15;
        const uint32_t so = sb + bufo + 2 * PV_AT + row * 272 + c * 16;
        const size_t g = (size_t)(kb + s * 64 + row) * DMODEL + d0 + c * 8;
        cpa16(so,         g_Vhi + g);
        cpa16(so + PV_BT, g_Vlo + g);
    }
    CP_COMMIT();
}

__global__ __launch_bounds__(256) void pv_kernel(float* __restrict__ Out)
{
    extern __shared__ char smc[];
    const uint32_t sb = smem_to_u32(smc);
    const int tid = threadIdx.x;
    const int l = tid & 31, w = tid >> 5;
    const int wy = w >> 2, wx = w & 3;
    const int q0 = blockIdx.y * 128;
    const int b  = q0 >> 11;
    const int kb = b * SEQ;
    const int d0 = blockIdx.x * 128;

    float C[4][4][4];
    #pragma unroll
    for (int mi = 0; mi < 4; mi++)
        #pragma unroll
        for (int ni = 0; ni < 4; ni++)
            #pragma unroll
            for (int q = 0; q < 4; q++) C[mi][ni][q] = 0.f;

    load_pv_stage(sb, 0,        tid, q0, kb, d0, 0);
    load_pv_stage(sb, PV_STAGE, tid, q0, kb, d0, 1);
    for (int s = 0; s < 32; s++) {
        if (s + 1 < 32) { CP_WAIT(1); } else { CP_WAIT(0); }
        __syncthreads();
        if (s + 2 < 32)
            load_pv_stage(sb, ((s + 2) % 3) * PV_STAGE, tid, q0, kb, d0, s + 2);
        const uint32_t bufo = (s % 3) * PV_STAGE;
        #pragma unroll
        for (int kk = 0; kk < 4; kk++) {
            uint32_t ph[4][4], pl[4][4];
            #pragma unroll
            for (int mi = 0; mi < 4; mi++) {
                const uint32_t ra = sb + bufo
                    + (uint32_t)(wy * 64 + mi * 16 + (l & 15)) * 144
                    + (uint32_t)(kk * 16 + ((l >> 4) << 3)) * 2;
                ldsm_x4(ph[mi], ra);
                ldsm_x4(pl[mi], ra + PV_AT);
            }
            #pragma unroll
            for (int ni = 0; ni < 4; ni++) {
                const uint32_t rb = sb + bufo + 2 * PV_AT
                    + (uint32_t)(kk * 16 + (l & 15)) * 272
                    + (uint32_t)(wx * 32 + ni * 8) * 2;
                uint32_t vh[2], vl[2];
                ldsm_x2t(vh, rb);
                ldsm_x2t(vl, rb + PV_BT);
                #pragma unroll
                for (int mi = 0; mi < 4; mi++) {
                    mma_bf16(C[mi][ni], ph[mi], vh);
                    mma_bf16(C[mi][ni], ph[mi], vl);
                    mma_bf16(C[mi][ni], pl[mi], vh);
                }
            }
        }
    }

    // epilogue: scale by 1/l and store
    #pragma unroll
    for (int mi = 0; mi < 4; mi++)
        #pragma unroll
        for (int h = 0; h < 2; h++) {
            const int r = q0 + wy * 64 + mi * 16 + h * 8 + (l >> 2);
            const float linv = __fdividef(1.f, g_l[r]);
            #pragma unroll
            for (int ni = 0; ni < 4; ni++) {
                const int c = d0 + wx * 32 + ni * 8 + 2 * (l & 3);
                float2 o;
                o.x = C[mi][ni][2 * h + 0] * linv;
                o.y = C[mi][ni][2 * h + 1] * linv;
                *(float2*)&Out[(size_t)r * DMODEL + c] = o;
            }
        }
}

// ---------------------------------------------------------------------------
extern "C" void kernel_launch(void* const* d_in, const int* in_sizes, int n_in,
                              void* d_out, int out_size)
{
    const float* X  = (const float*)d_in[0];
    const float* Wq = (const float*)d_in[1];
    const float* bq = (const float*)d_in[2];
    const float* Wk = (const float*)d_in[3];
    const float* bk = (const float*)d_in[4];
    const float* Wv = (const float*)d_in[5];
    const float* bv = (const float*)d_in[6];
    float* Out = (float*)d_out;

    split_x_kernel<<<NTOK * DMODEL / 4 / 256, 256>>>(X);
    splitT_w_kernel<<<dim3(32, 32, 3), dim3(32, 32)>>>(Wq, Wk, Wv);

    cudaFuncSetAttribute(qkv_mma_kernel, cudaFuncAttributeMaxDynamicSharedMemorySize, SMEM3);
    qkv_mma_kernel<<<dim3(DMODEL / 128, NTOK / 128, 3), 256, SMEM3>>>(bq, bk, bv);

    cudaFuncSetAttribute(sgemm_kernel, cudaFuncAttributeMaxDynamicSharedMemorySize, SMEM3);
    sgemm_kernel<<<dim3(SEQ / 128, NTOK / 128), 256, SMEM3>>>();

    softmax_kernel<<<NTOK, 256>>>();

    cudaFuncSetAttribute(pv_kernel, cudaFuncAttributeMaxDynamicSharedMemorySize, PV_SMEM);
    pv_kernel<<<dim3(DMODEL / 128, NTOK / 128), 256, PV_SMEM>>>(Out);
}

// round 7
// speedup vs baseline: 1.2393x; 1.0142x over previous
#include <cuda_runtime.h>
#include <cuda_bf16.h>
#include <cstdint>
#include <math.h>

// Problem constants
#define DMODEL 1024
#define NBATCH 8
#define SEQ    2048
#define NTOK   (NBATCH * SEQ)   // 16384

// split-bf16 global scratch
__device__ __nv_bfloat16 g_Xhi[NTOK * DMODEL];
__device__ __nv_bfloat16 g_Xlo[NTOK * DMODEL];
__device__ __nv_bfloat16 g_Wthi[3 * DMODEL * DMODEL];  // W^T, [z][n][k]
__device__ __nv_bfloat16 g_Wtlo[3 * DMODEL * DMODEL];
__device__ __nv_bfloat16 g_Qhi[NTOK * DMODEL];
__device__ __nv_bfloat16 g_Qlo[NTOK * DMODEL];
__device__ __nv_bfloat16 g_Khi[NTOK * DMODEL];
__device__ __nv_bfloat16 g_Klo[NTOK * DMODEL];
__device__ __nv_bfloat16 g_Vhi[NTOK * DMODEL];
__device__ __nv_bfloat16 g_Vlo[NTOK * DMODEL];
// attention intermediates
__device__ float         g_S[(size_t)NTOK * SEQ];     // scores, 134 MB
__device__ __nv_bfloat16 g_Phi[(size_t)NTOK * SEQ];   // exp(S-m), hi
__device__ __nv_bfloat16 g_Plo[(size_t)NTOK * SEQ];   // exp(S-m), lo
__device__ float         g_l[NTOK];                   // row sums

// ===========================================================================
// helpers
// ===========================================================================
__device__ __forceinline__ uint32_t smem_to_u32(const void* p) {
    uint32_t a;
    asm("{ .reg .u64 t; cvta.to.shared.u64 t, %1; cvt.u32.u64 %0, t; }" : "=r"(a) : "l"(p));
    return a;
}
__device__ __forceinline__ void cpa16(uint32_t d, const void* s) {
    asm volatile("cp.async.cg.shared.global [%0], [%1], 16;" :: "r"(d), "l"(s));
}
#define CP_COMMIT() asm volatile("cp.async.commit_group;")
#define CP_WAIT(N)  asm volatile("cp.async.wait_group %0;" :: "n"(N))

__device__ __forceinline__ void ldsm_x4(uint32_t r[4], uint32_t a) {
    asm volatile("ldmatrix.sync.aligned.m8n8.x4.shared.b16 {%0,%1,%2,%3}, [%4];"
        : "=r"(r[0]), "=r"(r[1]), "=r"(r[2]), "=r"(r[3]) : "r"(a));
}
__device__ __forceinline__ void ldsm_x2(uint32_t r[2], uint32_t a) {
    asm volatile("ldmatrix.sync.aligned.m8n8.x2.shared.b16 {%0,%1}, [%2];"
        : "=r"(r[0]), "=r"(r[1]) : "r"(a));
}
__device__ __forceinline__ void ldsm_x2t(uint32_t r[2], uint32_t a) {
    asm volatile("ldmatrix.sync.aligned.m8n8.x2.trans.shared.b16 {%0,%1}, [%2];"
        : "=r"(r[0]), "=r"(r[1]) : "r"(a));
}
__device__ __forceinline__ void mma_bf16(float c[4], const uint32_t a[4], const uint32_t b[2]) {
    asm volatile("mma.sync.aligned.m16n8k16.row.col.f32.bf16.bf16.f32 "
        "{%0,%1,%2,%3}, {%4,%5,%6,%7}, {%8,%9}, {%0,%1,%2,%3};"
        : "+f"(c[0]), "+f"(c[1]), "+f"(c[2]), "+f"(c[3])
        : "r"(a[0]), "r"(a[1]), "r"(a[2]), "r"(a[3]), "r"(b[0]), "r"(b[1]));
}

// ===========================================================================
// Tile geometry: CTA 128(M) x 256(N), K chunks of 64.
// A half-tile: 128 x 144B.  B half-tile: 256 x 144B.
// Stage = Ahi,Alo,Bhi,Blo = 110592 B; 2 stages = 221184 B smem.
// ===========================================================================
#define ATILE 18432
#define BTILE 36864
#define STAGE_G (2 * ATILE + 2 * BTILE)   // 110592
#define SMEM_G  (2 * STAGE_G)             // 221184

// Load one stage (256 threads): A/B row-major, k-contiguous, stride ld.
__device__ __forceinline__ void load_stageAB(
    uint32_t sb, uint32_t bufo, int tid,
    const __nv_bfloat16* A0, const __nv_bfloat16* A1,
    const __nv_bfloat16* B0, const __nv_bfloat16* B1,
    int ld, int arow0, int brow0, int dk)
{
    #pragma unroll
    for (int i = 0; i < 4; i++) {          // A: 128 rows x 8 c16
        const int idx = i * 256 + tid;
        const int row = idx >> 3;
        const int c   = idx & 7;
        const uint32_t so = sb + bufo + row * 144 + c * 16;
        const size_t ga = (size_t)(arow0 + row) * ld + dk + c * 8;
        cpa16(so,         A0 + ga);
        cpa16(so + ATILE, A1 + ga);
    }
    #pragma unroll
    for (int i = 0; i < 8; i++) {          // B: 256 rows x 8 c16
        const int idx = i * 256 + tid;
        const int row = idx >> 3;
        const int c   = idx & 7;
        const uint32_t so = sb + bufo + 2 * ATILE + row * 144 + c * 16;
        const size_t gb = (size_t)(brow0 + row) * ld + dk + c * 8;
        cpa16(so,         B0 + gb);
        cpa16(so + BTILE, B1 + gb);
    }
    CP_COMMIT();
}

// One K=64 compute stage, warp grid 2x4, warp tile 64x64, 3-term split.
__device__ __forceinline__ void mma_stage(
    float C[4][8][4], uint32_t sb, uint32_t bufo, int l, int wy, int wx)
{
    #pragma unroll
    for (int kk = 0; kk < 4; kk++) {
        uint32_t ah[4][4], al[4][4];
        #pragma unroll
        for (int mi = 0; mi < 4; mi++) {
            const uint32_t ra = sb + bufo
                + (uint32_t)(wy * 64 + mi * 16 + (l & 15)) * 144
                + (uint32_t)(kk * 16 + ((l >> 4) << 3)) * 2;
            ldsm_x4(ah[mi], ra);
            ldsm_x4(al[mi], ra + ATILE);
        }
        #pragma unroll
        for (int ni = 0; ni < 8; ni++) {
            const uint32_t rb = sb + bufo + 2 * ATILE
                + (uint32_t)(wx * 64 + ni * 8 + (l & 7)) * 144
                + (uint32_t)(kk * 16 + (((l >> 3) & 1) << 3)) * 2;
            uint32_t bh[2], bl[2];
            ldsm_x2(bh, rb);
            ldsm_x2(bl, rb + BTILE);
            #pragma unroll
            for (int mi = 0; mi < 4; mi++) {
                mma_bf16(C[mi][ni], ah[mi], bh);
                mma_bf16(C[mi][ni], ah[mi], bl);
                mma_bf16(C[mi][ni], al[mi], bh);
            }
        }
    }
}

// ===========================================================================
// Convert kernels
// ===========================================================================
__global__ __launch_bounds__(256) void split_x_kernel(const float* __restrict__ X) {
    const int i = blockIdx.x * 256 + threadIdx.x;   // over float4s
    float4 v = ((const float4*)X)[i];
    __nv_bfloat16 h0 = __float2bfloat16(v.x);
    __nv_bfloat16 h1 = __float2bfloat16(v.y);
    __nv_bfloat16 h2 = __float2bfloat16(v.z);
    __nv_bfloat16 h3 = __float2bfloat16(v.w);
    __nv_bfloat16 l0 = __float2bfloat16(v.x - __bfloat162float(h0));
    __nv_bfloat16 l1 = __float2bfloat16(v.y - __bfloat162float(h1));
    __nv_bfloat16 l2 = __float2bfloat16(v.z - __bfloat162float(h2));
    __nv_bfloat16 l3 = __float2bfloat16(v.w - __bfloat162float(h3));
    ((__nv_bfloat162*)g_Xhi)[i * 2 + 0] = __nv_bfloat162(h0, h1);
    ((__nv_bfloat162*)g_Xhi)[i * 2 + 1] = __nv_bfloat162(h2, h3);
    ((__nv_bfloat162*)g_Xlo)[i * 2 + 0] = __nv_bfloat162(l0, l1);
    ((__nv_bfloat162*)g_Xlo)[i * 2 + 1] = __nv_bfloat162(l2, l3);
}

__global__ void splitT_w_kernel(const float* __restrict__ Wq,
                                const float* __restrict__ Wk,
                                const float* __restrict__ Wv) {
    __shared__ float t[32][33];
    const int z = blockIdx.z;
    const float* W = (z == 0) ? Wq : (z == 1) ? Wk : Wv;
    const int k = blockIdx.y * 32 + threadIdx.y;
    const int n = blockIdx.x * 32 + threadIdx.x;
    t[threadIdx.y][threadIdx.x] = W[k * DMODEL + n];
    __syncthreads();
    const int on = blockIdx.x * 32 + threadIdx.y;   // output row (n)
    const int ok = blockIdx.y * 32 + threadIdx.x;   // output col (k)
    float v = t[threadIdx.x][threadIdx.y];
    __nv_bfloat16 h = __float2bfloat16(v);
    __nv_bfloat16 l = __float2bfloat16(v - __bfloat162float(h));
    g_Wthi[(size_t)z * DMODEL * DMODEL + on * DMODEL + ok] = h;
    g_Wtlo[(size_t)z * DMODEL * DMODEL + on * DMODEL + ok] = l;
}

// ===========================================================================
// Kernel 1: QKV projection. grid (4, 128, 3), 256 thr. CTA tile 128x256.
// ===========================================================================
__global__ __launch_bounds__(256) void qkv_mma_kernel(
    const float* __restrict__ bq, const float* __restrict__ bk,
    const float* __restrict__ bv)
{
    extern __shared__ char smc[];
    const uint32_t sb = smem_to_u32(smc);
    const int tid = threadIdx.x;
    const int l = tid & 31, w = tid >> 5;
    const int wy = w >> 2, wx = w & 3;
    const int z = blockIdx.z, m0 = blockIdx.y * 128, n0 = blockIdx.x * 256;

    const __nv_bfloat16* Bh = g_Wthi + (size_t)z * DMODEL * DMODEL;
    const __nv_bfloat16* Bl = g_Wtlo + (size_t)z * DMODEL * DMODEL;
    const float* bias = (z == 0) ? bq : (z == 1) ? bk : bv;
    __nv_bfloat16* ohi = (z == 0) ? g_Qhi : (z == 1) ? g_Khi : g_Vhi;
    __nv_bfloat16* olo = (z == 0) ? g_Qlo : (z == 1) ? g_Klo : g_Vlo;

    float C[4][8][4];
    #pragma unroll
    for (int mi = 0; mi < 4; mi++)
        #pragma unroll
        for (int ni = 0; ni < 8; ni++)
            #pragma unroll
            for (int q = 0; q < 4; q++) C[mi][ni][q] = 0.f;

    load_stageAB(sb, 0,       tid, g_Xhi, g_Xlo, Bh, Bl, DMODEL, m0, n0, 0);
    load_stageAB(sb, STAGE_G, tid, g_Xhi, g_Xlo, Bh, Bl, DMODEL, m0, n0, 64);
    for (int kc = 0; kc < 16; kc++) {
        if (kc + 1 < 16) { CP_WAIT(1); } else { CP_WAIT(0); }
        __syncthreads();
        mma_stage(C, sb, (kc & 1) * STAGE_G, l, wy, wx);
        __syncthreads();
        if (kc + 2 < 16)
            load_stageAB(sb, (kc & 1) * STAGE_G, tid, g_Xhi, g_Xlo, Bh, Bl,
                         DMODEL, m0, n0, (kc + 2) * 64);
    }

    // epilogue: bias add + hi/lo split store
    #pragma unroll
    for (int mi = 0; mi < 4; mi++)
        #pragma unroll
        for (int ni = 0; ni < 8; ni++)
            #pragma unroll
            for (int h = 0; h < 2; h++) {
                const int r = m0 + wy * 64 + mi * 16 + h * 8 + (l >> 2);
                const int c = n0 + wx * 64 + ni * 8 + 2 * (l & 3);
                const float v0 = C[mi][ni][2 * h + 0] + bias[c];
                const float v1 = C[mi][ni][2 * h + 1] + bias[c + 1];
                const __nv_bfloat16 h0 = __float2bfloat16(v0);
                const __nv_bfloat16 h1 = __float2bfloat16(v1);
                const __nv_bfloat16 l0 = __float2bfloat16(v0 - __bfloat162float(h0));
                const __nv_bfloat16 l1 = __float2bfloat16(v1 - __bfloat162float(h1));
                *(__nv_bfloat162*)&ohi[(size_t)r * DMODEL + c] = __nv_bfloat162(h0, h1);
                *(__nv_bfloat162*)&olo[(size_t)r * DMODEL + c] = __nv_bfloat162(l0, l1);
            }
}

// ===========================================================================
// Kernel 2: S = Q K^T. grid (8 k-tiles, 128 q-tiles), 256 thr. 128x256 tile.
// ===========================================================================
__global__ __launch_bounds__(256) void sgemm_kernel()
{
    extern __shared__ char smc[];
    const uint32_t sb = smem_to_u32(smc);
    const int tid = threadIdx.x;
    const int l = tid & 31, w = tid >> 5;
    const int wy = w >> 2, wx = w & 3;
    const int q0 = blockIdx.y * 128;              // global query row
    const int b  = q0 >> 11;                      // /2048
    const int k0 = b * SEQ + blockIdx.x * 256;    // global key row

    float C[4][8][4];
    #pragma unroll
    for (int mi = 0; mi < 4; mi++)
        #pragma unroll
        for (int ni = 0; ni < 8; ni++)
            #pragma unroll
            for (int q = 0; q < 4; q++) C[mi][ni][q] = 0.f;

    load_stageAB(sb, 0,       tid, g_Qhi, g_Qlo, g_Khi, g_Klo, DMODEL, q0, k0, 0);
    load_stageAB(sb, STAGE_G, tid, g_Qhi, g_Qlo, g_Khi, g_Klo, DMODEL, q0, k0, 64);
    for (int kc = 0; kc < 16; kc++) {
        if (kc + 1 < 16) { CP_WAIT(1); } else { CP_WAIT(0); }
        __syncthreads();
        mma_stage(C, sb, (kc & 1) * STAGE_G, l, wy, wx);
        __syncthreads();
        if (kc + 2 < 16)
            load_stageAB(sb, (kc & 1) * STAGE_G, tid, g_Qhi, g_Qlo,
                         g_Khi, g_Klo, DMODEL, q0, k0, (kc + 2) * 64);
    }

    // epilogue: store scores fp32
    #pragma unroll
    for (int mi = 0; mi < 4; mi++)
        #pragma unroll
        for (int ni = 0; ni < 8; ni++)
            #pragma unroll
            for (int h = 0; h < 2; h++) {
                const int r = q0 + wy * 64 + mi * 16 + h * 8 + (l >> 2);
                const int c = blockIdx.x * 256 + wx * 64 + ni * 8 + 2 * (l & 3);
                float2 s;
                s.x = C[mi][ni][2 * h + 0];
                s.y = C[mi][ni][2 * h + 1];
                *(float2*)&g_S[(size_t)r * SEQ + c] = s;
            }
}

// ===========================================================================
// Kernel 3: softmax rows. grid 16384, 256 thr.
// ===========================================================================
__global__ __launch_bounds__(256) void softmax_kernel()
{
    __shared__ float red[8];
    const int tid = threadIdx.x;
    const int lane = tid & 31, wrp = tid >> 5;
    const size_t row = blockIdx.x;
    const float* Sr = g_S + row * SEQ;

    float4 v0 = ((const float4*)Sr)[tid];
    float4 v1 = ((const float4*)Sr)[tid + 256];

    float m = fmaxf(fmaxf(fmaxf(v0.x, v0.y), fmaxf(v0.z, v0.w)),
                    fmaxf(fmaxf(v1.x, v1.y), fmaxf(v1.z, v1.w)));
    #pragma unroll
    for (int off = 16; off >= 1; off >>= 1)
        m = fmaxf(m, __shfl_xor_sync(0xffffffffu, m, off));
    if (lane == 0) red[wrp] = m;
    __syncthreads();
    float mm = red[0];
    #pragma unroll
    for (int i = 1; i < 8; i++) mm = fmaxf(mm, red[i]);
    __syncthreads();

    float e[8];
    e[0] = __expf(v0.x - mm); e[1] = __expf(v0.y - mm);
    e[2] = __expf(v0.z - mm); e[3] = __expf(v0.w - mm);
    e[4] = __expf(v1.x - mm); e[5] = __expf(v1.y - mm);
    e[6] = __expf(v1.z - mm); e[7] = __expf(v1.w - mm);

    float s = 0.f;
    #pragma unroll
    for (int i = 0; i < 8; i++) s += e[i];
    #pragma unroll
    for (int off = 16; off >= 1; off >>= 1)
        s += __shfl_xor_sync(0xffffffffu, s, off);
    if (lane == 0) red[wrp] = s;
    __syncthreads();
    if (tid == 0) {
        float tot = 0.f;
        #pragma unroll
        for (int i = 0; i < 8; i++) tot += red[i];
        g_l[row] = tot;
    }

    // write P hi/lo
    #pragma unroll
    for (int half = 0; half < 2; half++) {
        const size_t base = row * SEQ + (half * 256 + tid) * 4;
        #pragma unroll
        for (int j = 0; j < 2; j++) {
            const float a = e[half * 4 + 2 * j], bb = e[half * 4 + 2 * j + 1];
            const __nv_bfloat16 ah = __float2bfloat16(a);
            const __nv_bfloat16 bh = __float2bfloat16(bb);
            const __nv_bfloat16 al = __float2bfloat16(a - __bfloat162float(ah));
            const __nv_bfloat16 bl = __float2bfloat16(bb - __bfloat162float(bh));
            *(__nv_bfloat162*)&g_Phi[base + 2 * j] = __nv_bfloat162(ah, bh);
            *(__nv_bfloat162*)&g_Plo[base + 2 * j] = __nv_bfloat162(al, bl);
        }
    }
}

// ===========================================================================
// Kernel 4: O = (P V) / l. grid (4 d-tiles, 128 q-tiles), 256 thr.
// CTA tile 128(q) x 256(d); K = 2048 tokens, 32 stages of 64.
// V stage tile: 64 rows x 528 B (256 d cols + 16B pad), hi/lo.
// ===========================================================================
#define PV_BT 33792                          // 64 x 528
#define PV_STAGE (2 * ATILE + 2 * PV_BT)     // 104448
#define PV_SMEM (2 * PV_STAGE)               // 208896

__device__ __forceinline__ void load_pv_stage(
    uint32_t sb, uint32_t bufo, int tid, int q0, int kb, int d0, int s)
{
    #pragma unroll
    for (int i = 0; i < 4; i++) {            // P tiles: 128 rows x 64 cols
        const int idx = i * 256 + tid;
        const int row = idx >> 3;
        const int c   = idx & 7;
        const uint32_t so = sb + bufo + row * 144 + c * 16;
        const size_t g = (size_t)(q0 + row) * SEQ + s * 64 + c * 8;
        cpa16(so,         g_Phi + g);
        cpa16(so + ATILE, g_Plo + g);
    }
    #pragma unroll
    for (int i = 0; i < 8; i++) {            // V tiles: 64 rows x 256 cols
        const int idx = i * 256 + tid;
        const int row = idx >> 5;
        const int c   = idx & 31;
        const uint32_t so = sb + bufo + 2 * ATILE + row * 528 + c * 16;
        const size_t g = (size_t)(kb + s * 64 + row) * DMODEL + d0 + c * 8;
        cpa16(so,         g_Vhi + g);
        cpa16(so + PV_BT, g_Vlo + g);
    }
    CP_COMMIT();
}

__global__ __launch_bounds__(256) void pv_kernel(float* __restrict__ Out)
{
    extern __shared__ char smc[];
    const uint32_t sb = smem_to_u32(smc);
    const int tid = threadIdx.x;
    const int l = tid & 31, w = tid >> 5;
    const int wy = w >> 2, wx = w & 3;
    const int q0 = blockIdx.y * 128;
    const int b  = q0 >> 11;
    const int kb = b * SEQ;
    const int d0 = blockIdx.x * 256;

    float C[4][8][4];
    #pragma unroll
    for (int mi = 0; mi < 4; mi++)
        #pragma unroll
        for (int ni = 0; ni < 8; ni++)
            #pragma unroll
            for (int q = 0; q < 4; q++) C[mi][ni][q] = 0.f;

    load_pv_stage(sb, 0,        tid, q0, kb, d0, 0);
    load_pv_stage(sb, PV_STAGE, tid, q0, kb, d0, 1);
    for (int s = 0; s < 32; s++) {
        if (s + 1 < 32) { CP_WAIT(1); } else { CP_WAIT(0); }
        __syncthreads();
        const uint32_t bufo = (s & 1) * PV_STAGE;
        #pragma unroll
        for (int kk = 0; kk < 4; kk++) {
            uint32_t ph[4][4], pl[4][4];
            #pragma unroll
            for (int mi = 0; mi < 4; mi++) {
                const uint32_t ra = sb + bufo
                    + (uint32_t)(wy * 64 + mi * 16 + (l & 15)) * 144
                    + (uint32_t)(kk * 16 + ((l >> 4) << 3)) * 2;
                ldsm_x4(ph[mi], ra);
                ldsm_x4(pl[mi], ra + ATILE);
            }
            #pragma unroll
            for (int ni = 0; ni < 8; ni++) {
                const uint32_t rb = sb + bufo + 2 * ATILE
                    + (uint32_t)(kk * 16 + (l & 15)) * 528
                    + (uint32_t)(wx * 64 + ni * 8) * 2;
                uint32_t vh[2], vl[2];
                ldsm_x2t(vh, rb);
                ldsm_x2t(vl, rb + PV_BT);
                #pragma unroll
                for (int mi = 0; mi < 4; mi++) {
                    mma_bf16(C[mi][ni], ph[mi], vh);
                    mma_bf16(C[mi][ni], ph[mi], vl);
                    mma_bf16(C[mi][ni], pl[mi], vh);
                }
            }
        }
        __syncthreads();
        if (s + 2 < 32)
            load_pv_stage(sb, (s & 1) * PV_STAGE, tid, q0, kb, d0, s + 2);
    }

    // epilogue: scale by 1/l and store
    #pragma unroll
    for (int mi = 0; mi < 4; mi++)
        #pragma unroll
        for (int h = 0; h < 2; h++) {
            const int r = q0 + wy * 64 + mi * 16 + h * 8 + (l >> 2);
            const float linv = __fdividef(1.f, g_l[r]);
            #pragma unroll
            for (int ni = 0; ni < 8; ni++) {
                const int c = d0 + wx * 64 + ni * 8 + 2 * (l & 3);
                float2 o;
                o.x = C[mi][ni][2 * h + 0] * linv;
                o.y = C[mi][ni][2 * h + 1] * linv;
                *(float2*)&Out[(size_t)r * DMODEL + c] = o;
            }
        }
}

// ---------------------------------------------------------------------------
extern "C" void kernel_launch(void* const* d_in, const int* in_sizes, int n_in,
                              void* d_out, int out_size)
{
    const float* X  = (const float*)d_in[0];
    const float* Wq = (const float*)d_in[1];
    const float* bq = (const float*)d_in[2];
    const float* Wk = (const float*)d_in[3];
    const float* bk = (const float*)d_in[4];
    const float* Wv = (const float*)d_in[5];
    const float* bv = (const float*)d_in[6];
    float* Out = (float*)d_out;

    split_x_kernel<<<NTOK * DMODEL / 4 / 256, 256>>>(X);
    splitT_w_kernel<<<dim3(32, 32, 3), dim3(32, 32)>>>(Wq, Wk, Wv);

    cudaFuncSetAttribute(qkv_mma_kernel, cudaFuncAttributeMaxDynamicSharedMemorySize, SMEM_G);
    qkv_mma_kernel<<<dim3(DMODEL / 256, NTOK / 128, 3), 256, SMEM_G>>>(bq, bk, bv);

    cudaFuncSetAttribute(sgemm_kernel, cudaFuncAttributeMaxDynamicSharedMemorySize, SMEM_G);
    sgemm_kernel<<<dim3(SEQ / 256, NTOK / 128), 256, SMEM_G>>>();

    softmax_kernel<<<NTOK, 256>>>();

    cudaFuncSetAttribute(pv_kernel, cudaFuncAttributeMaxDynamicSharedMemorySize, PV_SMEM);
    pv_kernel<<<dim3(DMODEL / 256, NTOK / 128), 256, PV_SMEM>>>(Out);
}